// round 12
// baseline (speedup 1.0000x reference)
#include <cuda_runtime.h>
#include <cooperative_groups.h>
namespace cg = cooperative_groups;
typedef unsigned long long ull;

#define TT 1200
#define HH 128
#define II 16
#define CSIZE 4
#define BC 8
#define NT 512
#define NCTAS 128

struct __align__(16) Smem {
    float Whh0[HH * HH];      // [k][jj*4+g]
    float Wih1[HH * HH];
    float Whh1[HH * HH];
    float b0[HH], b1[HH];
    float h0buf[2][HH * BC];  // [par][k*BC+b]
    float h1buf[2][HH * BC];
    ull   red[3 * 32 * 16];
    float2 headred[2][16][4];
    ull   mbars[18];          // [0..7]=h0[par][srcq]  [8..15]=h1[par][srcq]  [16..17]=head[par]
};

__device__ __forceinline__ float sig_f(float x) {
    return __fdividef(1.0f, 1.0f + __expf(-x));
}
__device__ __forceinline__ float tanh_f(float x) {
    return __fdividef(2.0f, 1.0f + __expf(-2.0f * x)) - 1.0f;
}
__device__ __forceinline__ ull bcast2(float f) {
    ull r; asm("mov.b64 %0, {%1, %1};" : "=l"(r) : "f"(f)); return r;
}
__device__ __forceinline__ ull pack2(float a, float b) {
    ull r; asm("mov.b64 %0, {%1, %2};" : "=l"(r) : "f"(a), "f"(b)); return r;
}
__device__ __forceinline__ void fma2(ull& a, ull b, ull c) {
    asm("fma.rn.f32x2 %0, %1, %2, %0;" : "+l"(a) : "l"(b), "l"(c));
}
__device__ __forceinline__ ull add2(ull a, ull b) {
    ull r; asm("add.rn.f32x2 %0, %1, %2;" : "=l"(r) : "l"(a), "l"(b)); return r;
}
__device__ __forceinline__ void unpack2(ull v, float& lo, float& hi) {
    asm("mov.b64 {%0, %1}, %2;" : "=f"(lo), "=f"(hi) : "l"(v));
}
__device__ __forceinline__ uint32_t smem_u32(const void* p) {
    uint32_t a;
    asm("{ .reg .u64 t; cvta.to.shared.u64 t, %1; cvt.u32.u64 %0, t; }"
        : "=r"(a) : "l"(p));
    return a;
}
__device__ __forceinline__ uint32_t mapa_rank(uint32_t a, int r) {
    uint32_t d;
    asm("mapa.shared::cluster.u32 %0, %1, %2;" : "=r"(d) : "r"(a), "r"(r));
    return d;
}
#define MB_INIT(mb) \
    asm volatile("mbarrier.init.shared.b64 [%0], 1;" :: "r"(mb) : "memory")
#define MB_ARM(mb, tx) \
    asm volatile("mbarrier.arrive.expect_tx.shared.b64 _, [%0], %1;" \
                 :: "r"(mb), "r"(tx) : "memory")
#define MB_WAIT(mb, par) do { \
    asm volatile( \
        "{\n\t.reg .pred P;\n\t" \
        "W_%=:\n\t" \
        "mbarrier.try_wait.parity.acquire.cta.shared::cta.b64 P, [%0], %1, 0x989680;\n\t" \
        "@P bra.uni D_%=;\n\t" \
        "bra.uni W_%=;\n\t" \
        "D_%=:\n\t}" \
        :: "r"(mb), "r"(par) : "memory"); \
} while (0)
#define ST_ASYNC8(da, v, mb) \
    asm volatile("st.async.shared::cluster.mbarrier::complete_tx::bytes.b64 [%0], %1, [%2];" \
                 :: "r"(da), "l"(v), "r"(mb) : "memory")

// acc += W * src over full 8-k slice.
__device__ __forceinline__ void accumH(ull acc[4][4], const float* __restrict__ W,
                                       const float* __restrict__ S, int ks, int lroff) {
    const float* Wp = W + ks * 8 * HH + lroff;
    const float* Sp = S + ks * 8 * BC;
#pragma unroll
    for (int k = 0; k < 8; k++) {
        float4 wv = *(const float4*)(Wp + k * HH);
        ulonglong2 sa = *(const ulonglong2*)(Sp + k * BC);
        ulonglong2 sb = *(const ulonglong2*)(Sp + k * BC + 4);
        ull w0 = bcast2(wv.x), w1 = bcast2(wv.y), w2 = bcast2(wv.z), w3 = bcast2(wv.w);
        fma2(acc[0][0], w0, sa.x); fma2(acc[0][1], w0, sa.y);
        fma2(acc[0][2], w0, sb.x); fma2(acc[0][3], w0, sb.y);
        fma2(acc[1][0], w1, sa.x); fma2(acc[1][1], w1, sa.y);
        fma2(acc[1][2], w1, sb.x); fma2(acc[1][3], w1, sb.y);
        fma2(acc[2][0], w2, sa.x); fma2(acc[2][1], w2, sa.y);
        fma2(acc[2][2], w2, sb.x); fma2(acc[2][3], w2, sb.y);
        fma2(acc[3][0], w3, sa.x); fma2(acc[3][1], w3, sa.y);
        fma2(acc[3][2], w3, sb.x); fma2(acc[3][3], w3, sb.y);
    }
}

// k 0..5: fused dual accumulate (a1 += W1*src, a0 += W0*src), src loaded once.
__device__ __forceinline__ void accumA(ull a1[4][4], ull a0[4][4],
                                       const float* __restrict__ W1,
                                       const float* __restrict__ W0,
                                       const float* __restrict__ S, int ks, int lroff) {
    const float* Wp1 = W1 + ks * 8 * HH + lroff;
    const float* Wp0 = W0 + ks * 8 * HH + lroff;
    const float* Sp = S + ks * 8 * BC;
#pragma unroll
    for (int k = 0; k < 6; k++) {
        float4 w1 = *(const float4*)(Wp1 + k * HH);
        float4 w0 = *(const float4*)(Wp0 + k * HH);
        ulonglong2 sa = *(const ulonglong2*)(Sp + k * BC);
        ulonglong2 sb = *(const ulonglong2*)(Sp + k * BC + 4);
        ull b0 = bcast2(w1.x), b1 = bcast2(w1.y), b2 = bcast2(w1.z), b3 = bcast2(w1.w);
        fma2(a1[0][0], b0, sa.x); fma2(a1[0][1], b0, sa.y);
        fma2(a1[0][2], b0, sb.x); fma2(a1[0][3], b0, sb.y);
        fma2(a1[1][0], b1, sa.x); fma2(a1[1][1], b1, sa.y);
        fma2(a1[1][2], b1, sb.x); fma2(a1[1][3], b1, sb.y);
        fma2(a1[2][0], b2, sa.x); fma2(a1[2][1], b2, sa.y);
        fma2(a1[2][2], b2, sb.x); fma2(a1[2][3], b2, sb.y);
        fma2(a1[3][0], b3, sa.x); fma2(a1[3][1], b3, sa.y);
        fma2(a1[3][2], b3, sb.x); fma2(a1[3][3], b3, sb.y);
        ull c0 = bcast2(w0.x), c1 = bcast2(w0.y), c2 = bcast2(w0.z), c3 = bcast2(w0.w);
        fma2(a0[0][0], c0, sa.x); fma2(a0[0][1], c0, sa.y);
        fma2(a0[0][2], c0, sb.x); fma2(a0[0][3], c0, sb.y);
        fma2(a0[1][0], c1, sa.x); fma2(a0[1][1], c1, sa.y);
        fma2(a0[1][2], c1, sb.x); fma2(a0[1][3], c1, sb.y);
        fma2(a0[2][0], c2, sa.x); fma2(a0[2][1], c2, sa.y);
        fma2(a0[2][2], c2, sb.x); fma2(a0[2][3], c2, sb.y);
        fma2(a0[3][0], c3, sa.x); fma2(a0[3][1], c3, sa.y);
        fma2(a0[3][2], c3, sb.x); fma2(a0[3][3], c3, sb.y);
    }
}

// k 6..7: a1 += W1*src, parking src in sreg[8].
__device__ __forceinline__ void accumB(ull a1[4][4], const float* __restrict__ W1,
                                       const float* __restrict__ S, int ks, int lroff,
                                       ull* __restrict__ sreg) {
    const float* Wp1 = W1 + ks * 8 * HH + lroff;
    const float* Sp = S + ks * 8 * BC;
#pragma unroll
    for (int k = 0; k < 2; k++) {
        const int kk = k + 6;
        float4 w1 = *(const float4*)(Wp1 + kk * HH);
        ulonglong2 sa = *(const ulonglong2*)(Sp + kk * BC);
        ulonglong2 sb = *(const ulonglong2*)(Sp + kk * BC + 4);
        sreg[k * 4 + 0] = sa.x; sreg[k * 4 + 1] = sa.y;
        sreg[k * 4 + 2] = sb.x; sreg[k * 4 + 3] = sb.y;
        ull b0 = bcast2(w1.x), b1 = bcast2(w1.y), b2 = bcast2(w1.z), b3 = bcast2(w1.w);
        fma2(a1[0][0], b0, sa.x); fma2(a1[0][1], b0, sa.y);
        fma2(a1[0][2], b0, sb.x); fma2(a1[0][3], b0, sb.y);
        fma2(a1[1][0], b1, sa.x); fma2(a1[1][1], b1, sa.y);
        fma2(a1[1][2], b1, sb.x); fma2(a1[1][3], b1, sb.y);
        fma2(a1[2][0], b2, sa.x); fma2(a1[2][1], b2, sa.y);
        fma2(a1[2][2], b2, sb.x); fma2(a1[2][3], b2, sb.y);
        fma2(a1[3][0], b3, sa.x); fma2(a1[3][1], b3, sa.y);
        fma2(a1[3][2], b3, sb.x); fma2(a1[3][3], b3, sb.y);
    }
}

// k 6..7: a0 += W0*sreg (weight loads only).
__device__ __forceinline__ void accumC(ull a0[4][4], const float* __restrict__ W0,
                                       int ks, int lroff, const ull* __restrict__ sreg) {
    const float* Wp0 = W0 + ks * 8 * HH + lroff;
#pragma unroll
    for (int k = 0; k < 2; k++) {
        const int kk = k + 6;
        float4 w0 = *(const float4*)(Wp0 + kk * HH);
        ull s0 = sreg[k * 4 + 0], s1 = sreg[k * 4 + 1];
        ull s2 = sreg[k * 4 + 2], s3 = sreg[k * 4 + 3];
        ull c0 = bcast2(w0.x), c1 = bcast2(w0.y), c2 = bcast2(w0.z), c3 = bcast2(w0.w);
        fma2(a0[0][0], c0, s0); fma2(a0[0][1], c0, s1);
        fma2(a0[0][2], c0, s2); fma2(a0[0][3], c0, s3);
        fma2(a0[1][0], c1, s0); fma2(a0[1][1], c1, s1);
        fma2(a0[1][2], c1, s2); fma2(a0[1][3], c1, s3);
        fma2(a0[2][0], c2, s0); fma2(a0[2][1], c2, s1);
        fma2(a0[2][2], c2, s2); fma2(a0[2][3], c2, s3);
        fma2(a0[3][0], c3, s0); fma2(a0[3][1], c3, s1);
        fma2(a0[3][2], c3, s2); fma2(a0[3][3], c3, s3);
    }
}

// Reduce + gates + c update + st.async h to all ranks under per-source mbarrier.
template <bool HEAD, int BARID>
__device__ __forceinline__ void rus(ull acc[4][4], Smem* sm, const float* __restrict__ bias,
                                    float2& cp, const uint32_t* dbase,
                                    uint32_t h_off, uint32_t mb_off,
                                    uint32_t hd_off, uint32_t mbh_off,
                                    int q, int warp, int lane, float wl) {
    ull o4[4];
    {
        const bool h8 = lane & 8;
        ull m0[4], m1[4];
#pragma unroll
        for (int g = 0; g < 4; g++) {
            ull s0 = h8 ? acc[g][0] : acc[g][2];
            ull s1 = h8 ? acc[g][1] : acc[g][3];
            ull r0 = __shfl_xor_sync(0xffffffffu, s0, 8);
            ull r1 = __shfl_xor_sync(0xffffffffu, s1, 8);
            m0[g] = add2(h8 ? acc[g][2] : acc[g][0], r0);
            m1[g] = add2(h8 ? acc[g][3] : acc[g][1], r1);
        }
        const bool h16 = lane & 16;
#pragma unroll
        for (int g = 0; g < 4; g++) {
            ull s = h16 ? m0[g] : m1[g];
            ull r = __shfl_xor_sync(0xffffffffu, s, 16);
            o4[g] = add2(h16 ? m1[g] : m0[g], r);
        }
    }
    const int jjl = lane & 7, wg = warp & 3, ksr = warp >> 2;
    const int jj = wg * 8 + jjl;
    const int pi = ((lane >> 3) & 1) * 2 + ((lane >> 4) & 1);
    if (ksr > 0) {
        ull* slot = sm->red + ((ksr - 1) * 32 + jj) * 16 + (pi ^ (jjl & 3)) * 4;
        *(ulonglong2*)(slot)     = make_ulonglong2(o4[0], o4[1]);
        *(ulonglong2*)(slot + 2) = make_ulonglong2(o4[2], o4[3]);
        asm volatile("bar.arrive %0, %1;" :: "n"(BARID), "n"(NT) : "memory");
    } else {
        asm volatile("bar.sync %0, %1;" :: "n"(BARID), "n"(NT) : "memory");
        ull* slot = sm->red + jj * 16 + (pi ^ (jjl & 3)) * 4;
#pragma unroll
        for (int r = 0; r < 3; r++) {
            ulonglong2 v0 = *(ulonglong2*)(slot + r * 512);
            ulonglong2 v1 = *(ulonglong2*)(slot + r * 512 + 2);
            o4[0] = add2(o4[0], v0.x); o4[1] = add2(o4[1], v0.y);
            o4[2] = add2(o4[2], v1.x); o4[3] = add2(o4[3], v1.y);
        }
        float4 bq = *(const float4*)(bias + jj * 4);
        float xi0, xi1, xf0, xf1, xg0, xg1, xo0, xo1;
        unpack2(o4[0], xi0, xi1); unpack2(o4[1], xf0, xf1);
        unpack2(o4[2], xg0, xg1); unpack2(o4[3], xo0, xo1);
        float i0 = sig_f(xi0 + bq.x), i1 = sig_f(xi1 + bq.x);
        float f0 = sig_f(xf0 + bq.y), f1 = sig_f(xf1 + bq.y);
        float g0 = tanh_f(xg0 + bq.z), g1 = tanh_f(xg1 + bq.z);
        float o0 = sig_f(xo0 + bq.w), o1 = sig_f(xo1 + bq.w);
        cp.x = f0 * cp.x + i0 * g0;
        cp.y = f1 * cp.y + i1 * g1;
        float h0v = o0 * tanh_f(cp.x), h1v = o1 * tanh_f(cp.y);
        ull hp = pack2(h0v, h1v);
        uint32_t row = h_off + ((q * 32 + jj) * BC + pi * 2) * 4;
#pragma unroll
        for (int r2 = 0; r2 < CSIZE; r2++)
            ST_ASYNC8(dbase[r2] + row, hp, dbase[r2] + mb_off);
        if (HEAD) {
            ull hh = pack2(fmaxf(h0v, 0.f) * wl, fmaxf(h1v, 0.f) * wl);
            hh = add2(hh, __shfl_xor_sync(0xffffffffu, hh, 1));
            hh = add2(hh, __shfl_xor_sync(0xffffffffu, hh, 2));
            hh = add2(hh, __shfl_xor_sync(0xffffffffu, hh, 4));
            if (jjl == 0)
                ST_ASYNC8(dbase[0] + hd_off + ((q * 4 + wg) * 4 + pi) * 8, hh,
                          dbase[0] + mbh_off);
        }
    }
}

__device__ __forceinline__ void head_out(Smem* sm, int par, float* __restrict__ out,
                                         int bbase, float blinr, int lane, int tt) {
    int g = lane >> 4, l = lane & 15;
    float2 v0 = sm->headred[par][l][g * 2 + 0];
    float2 v1 = sm->headred[par][l][g * 2 + 1];
    ull a = pack2(v0.x, v0.y), b = pack2(v1.x, v1.y);
#pragma unroll
    for (int m = 1; m <= 8; m <<= 1) {
        a = add2(a, __shfl_xor_sync(0xffffffffu, a, m));
        b = add2(b, __shfl_xor_sync(0xffffffffu, b, m));
    }
    if (l == 0) {
        float a0, a1, b0, b1;
        unpack2(a, a0, a1); unpack2(b, b0, b1);
        size_t base = (size_t)(bbase + g * 4) * TT + tt;
        out[base]          = a0 + blinr;
        out[base + TT]     = a1 + blinr;
        out[base + 2 * TT] = b0 + blinr;
        out[base + 3 * TT] = b1 + blinr;
    }
}

__global__ void __cluster_dims__(CSIZE, 1, 1) __launch_bounds__(NT, 1)
lstm_kernel(const float* __restrict__ x,
            const float* __restrict__ Wih0, const float* __restrict__ Whh0,
            const float* __restrict__ bih0, const float* __restrict__ bhh0,
            const float* __restrict__ Wih1, const float* __restrict__ Whh1,
            const float* __restrict__ bih1, const float* __restrict__ bhh1,
            const float* __restrict__ Wlin, const float* __restrict__ blin,
            float* __restrict__ out) {
    extern __shared__ char smem_bytes[];
    Smem* sm = (Smem*)smem_bytes;
    cg::cluster_group cl = cg::this_cluster();
    const int q = cl.block_rank();
    const int tid = threadIdx.x, warp = tid >> 5, lane = tid & 31;
    const int bbase = (blockIdx.x / CSIZE) * BC;

    for (int idx = tid; idx < HH * HH; idx += NT) {
        int k = idx >> 7, lr = idx & 127;
        int g = lr & 3, j2 = lr >> 2;
        int grow = g * HH + q * 32 + j2;
        sm->Whh0[k * HH + lr] = Whh0[grow * HH + k];
        sm->Wih1[k * HH + lr] = Wih1[grow * HH + k];
        sm->Whh1[k * HH + lr] = Whh1[grow * HH + k];
    }
    for (int lr = tid; lr < HH; lr += NT) {
        int g = lr & 3, j2 = lr >> 2;
        int grow = g * HH + q * 32 + j2;
        sm->b0[lr] = bih0[grow] + bhh0[grow];
        sm->b1[lr] = bih1[grow] + bhh1[grow];
    }
    for (int i = tid; i < 2 * HH * BC; i += NT) {
        ((float*)sm->h0buf)[i] = 0.0f;
        ((float*)sm->h1buf)[i] = 0.0f;
    }
    const int jj = (warp & 3) * 8 + (lane & 7);
    const int lroff = jj * 4;
    const int ksr = warp >> 2;
    const int ks = ksr * 4 + ((lane >> 3) & 3);

    ull wih0p[4];
#pragma unroll
    for (int g = 0; g < 4; g++)
        wih0p[g] = bcast2(Wih0[(g * HH + q * 32 + jj) * II + ks]);
    const float wl = Wlin[q * 32 + jj];
    const float blinr = blin[0];

    const uint32_t sb = smem_u32(smem_bytes);
    uint32_t dbase[CSIZE];
#pragma unroll
    for (int r = 0; r < CSIZE; r++) dbase[r] = mapa_rank(sb, r);
    const uint32_t h0off = (uint32_t)((char*)&sm->h0buf[0][0] - smem_bytes);
    const uint32_t h1off = (uint32_t)((char*)&sm->h1buf[0][0] - smem_bytes);
    const uint32_t hroff = (uint32_t)((char*)&sm->headred[0][0][0] - smem_bytes);
    const uint32_t mboff = (uint32_t)((char*)&sm->mbars[0] - smem_bytes);
    const uint32_t mb_l = sb + mboff;

    if (tid == 0) {
#pragma unroll
        for (int i = 0; i < 18; i++) MB_INIT(mb_l + i * 8);
#pragma unroll
        for (int i = 0; i < 16; i++) MB_ARM(mb_l + i * 8, 1024);
        if (q == 0) { MB_ARM(mb_l + 128, 512); MB_ARM(mb_l + 136, 512); }
    }
    __syncthreads();
    cl.sync();

    float2 c0 = {0.f, 0.f}, c1 = {0.f, 0.f};
    const float* xbase = x + (size_t)bbase * TT * II + ks;
    const bool rearm = ((warp & 3) == 0) && (lane == 0);

    float xr[8];
#pragma unroll
    for (int b = 0; b < 8; b++) xr[b] = __ldg(xbase + b * TT * II);
    ull acc0[4][4];
    {
        ull s0 = pack2(xr[0], xr[1]), s1 = pack2(xr[2], xr[3]);
        ull s2 = pack2(xr[4], xr[5]), s3 = pack2(xr[6], xr[7]);
#pragma unroll
        for (int g = 0; g < 4; g++) {
            acc0[g][0] = 0ull; acc0[g][1] = 0ull; acc0[g][2] = 0ull; acc0[g][3] = 0ull;
            fma2(acc0[g][0], wih0p[g], s0); fma2(acc0[g][1], wih0p[g], s1);
            fma2(acc0[g][2], wih0p[g], s2); fma2(acc0[g][3], wih0p[g], s3);
        }
    }

    for (int t = 0; t < TT; t++) {
        const int par = t & 1, nxt = par ^ 1;
        const uint32_t pw0 = (t >> 1) & 1;
        const uint32_t pw1 = ((t - 1) >> 1) & 1;

        // prefetch x(t+1)
        {
            const float* xp = xbase + (size_t)((t + 1 < TT) ? t + 1 : TT - 1) * II;
#pragma unroll
            for (int b = 0; b < 8; b++) xr[b] = __ldg(xp + b * TT * II);
        }

        // quarter-wise wait: h1(t-1) quarter ksr (+ own-q for red safety)
        if (t > 0) {
            const uint32_t mb1 = mb_l + 64 + nxt * 32;
            MB_WAIT(mb1 + ksr * 8, pw1);
            if (q != ksr) MB_WAIT(mb1 + q * 8, pw1);
            if (rearm) MB_ARM(mb1 + ksr * 8, 1024);
        }

        // layer-0 reduce -> push h0(t) under per-source mb (quarter = own q)
        rus<false, 1>(acc0, sm, sm->b0, c0, dbase,
                      h0off + par * (HH * BC * 4), mboff + (par * 4 + q) * 8,
                      0, 0, q, warp, lane, 0.f);

        ull acc1[4][4];
#pragma unroll
        for (int g = 0; g < 4; g++) {
            acc1[g][0] = 0ull; acc1[g][1] = 0ull; acc1[g][2] = 0ull; acc1[g][3] = 0ull;
        }
        accumH(acc1, sm->Whh1, sm->h1buf[nxt], ks, lroff);

        // acc0 = Wih0 * x(t+1)
        {
            ull s0 = pack2(xr[0], xr[1]), s1 = pack2(xr[2], xr[3]);
            ull s2 = pack2(xr[4], xr[5]), s3 = pack2(xr[6], xr[7]);
#pragma unroll
            for (int g = 0; g < 4; g++) {
                acc0[g][0] = 0ull; acc0[g][1] = 0ull; acc0[g][2] = 0ull; acc0[g][3] = 0ull;
                fma2(acc0[g][0], wih0p[g], s0); fma2(acc0[g][1], wih0p[g], s1);
                fma2(acc0[g][2], wih0p[g], s2); fma2(acc0[g][3], wih0p[g], s3);
            }
        }

        // quarter-wise wait: h0(t) quarter ksr (+ own-q for red safety)
        {
            const uint32_t mb0 = mb_l + par * 32;
            MB_WAIT(mb0 + ksr * 8, pw0);
            if (q != ksr) MB_WAIT(mb0 + q * 8, pw0);
            if (rearm) MB_ARM(mb0 + ksr * 8, 1024);
        }

        // h0(t) read once: dual-fused k0-5, parked k6-7
        accumA(acc1, acc0, sm->Wih1, sm->Whh0, sm->h0buf[par], ks, lroff);
        ull sreg[8];
        accumB(acc1, sm->Wih1, sm->h0buf[par], ks, lroff, sreg);

        rus<true, 2>(acc1, sm, sm->b1, c1, dbase,
                     h1off + par * (HH * BC * 4), mboff + 64 + (par * 4 + q) * 8,
                     hroff + par * 512, mboff + 128 + par * 8,
                     q, warp, lane, wl);

        accumC(acc0, sm->Whh0, ks, lroff, sreg);

        if (q == 0 && warp == 15 && t > 0) {
            MB_WAIT(mb_l + 128 + nxt * 8, pw1);
            if (lane == 0) MB_ARM(mb_l + 128 + nxt * 8, 512);
            head_out(sm, nxt, out, bbase, blinr, lane, t - 1);
        }
    }
    if (q == 0 && warp == 15) {
        MB_WAIT(mb_l + 128 + ((TT - 1) & 1) * 8, ((TT - 1) >> 1) & 1);
        head_out(sm, (TT - 1) & 1, out, bbase, blinr, lane, TT - 1);
    }
    cl.sync();
}

extern "C" void kernel_launch(void* const* d_in, const int* in_sizes, int n_in,
                              void* d_out, int out_size) {
    const float* x    = (const float*)d_in[0];
    const float* Wih0 = (const float*)d_in[1];
    const float* Whh0 = (const float*)d_in[2];
    const float* bih0 = (const float*)d_in[3];
    const float* bhh0 = (const float*)d_in[4];
    const float* Wih1 = (const float*)d_in[5];
    const float* Whh1 = (const float*)d_in[6];
    const float* bih1 = (const float*)d_in[7];
    const float* bhh1 = (const float*)d_in[8];
    const float* Wlin = (const float*)d_in[9];
    const float* blin = (const float*)d_in[10];
    float* out = (float*)d_out;

    size_t smem = sizeof(Smem);
    cudaFuncSetAttribute(lstm_kernel, cudaFuncAttributeMaxDynamicSharedMemorySize,
                         (int)smem);
    lstm_kernel<<<NCTAS, NT, smem>>>(x, Wih0, Whh0, bih0, bhh0,
                                     Wih1, Whh1, bih1, bhh1,
                                     Wlin, blin, out);
}

// round 13
// speedup vs baseline: 1.0860x; 1.0860x over previous
#include <cuda_runtime.h>
#include <cooperative_groups.h>
namespace cg = cooperative_groups;
typedef unsigned long long ull;

#define TT 1200
#define HH 128
#define II 16
#define CSIZE 4
#define BC 8
#define NT 512
#define NCTAS 128

struct __align__(16) Smem {
    float Whh0[HH * HH];      // [k][jj*4+g]
    float Wih1[HH * HH];
    float Whh1[HH * HH];
    float b0[HH], b1[HH];
    float h0buf[2][HH * BC];  // [par][k*BC+b]
    float h1buf[2][HH * BC];
    ull   red[3 * 32 * 16];
    float2 headred[2][16][4];
    ull   mbars[6];           // 0,1: h0[par]  2,3: h1[par]  4,5: head[par]
};

__device__ __forceinline__ float sig_f(float x) {
    return __fdividef(1.0f, 1.0f + __expf(-x));
}
__device__ __forceinline__ float tanh_f(float x) {
    return __fdividef(2.0f, 1.0f + __expf(-2.0f * x)) - 1.0f;
}
__device__ __forceinline__ ull bcast2(float f) {
    ull r; asm("mov.b64 %0, {%1, %1};" : "=l"(r) : "f"(f)); return r;
}
__device__ __forceinline__ ull pack2(float a, float b) {
    ull r; asm("mov.b64 %0, {%1, %2};" : "=l"(r) : "f"(a), "f"(b)); return r;
}
__device__ __forceinline__ void fma2(ull& a, ull b, ull c) {
    asm("fma.rn.f32x2 %0, %1, %2, %0;" : "+l"(a) : "l"(b), "l"(c));
}
__device__ __forceinline__ ull add2(ull a, ull b) {
    ull r; asm("add.rn.f32x2 %0, %1, %2;" : "=l"(r) : "l"(a), "l"(b)); return r;
}
__device__ __forceinline__ void unpack2(ull v, float& lo, float& hi) {
    asm("mov.b64 {%0, %1}, %2;" : "=f"(lo), "=f"(hi) : "l"(v));
}
__device__ __forceinline__ uint32_t smem_u32(const void* p) {
    uint32_t a;
    asm("{ .reg .u64 t; cvta.to.shared.u64 t, %1; cvt.u32.u64 %0, t; }"
        : "=r"(a) : "l"(p));
    return a;
}
__device__ __forceinline__ uint32_t mapa_rank(uint32_t a, int r) {
    uint32_t d;
    asm("mapa.shared::cluster.u32 %0, %1, %2;" : "=r"(d) : "r"(a), "r"(r));
    return d;
}
#define MB_INIT(mb) \
    asm volatile("mbarrier.init.shared.b64 [%0], 1;" :: "r"(mb) : "memory")
#define MB_ARM(mb, tx) \
    asm volatile("mbarrier.arrive.expect_tx.shared.b64 _, [%0], %1;" \
                 :: "r"(mb), "r"(tx) : "memory")
#define MB_WAIT(mb, par) do { \
    asm volatile( \
        "{\n\t.reg .pred P;\n\t" \
        "W_%=:\n\t" \
        "mbarrier.try_wait.parity.acquire.cta.shared::cta.b64 P, [%0], %1, 0x989680;\n\t" \
        "@P bra.uni D_%=;\n\t" \
        "bra.uni W_%=;\n\t" \
        "D_%=:\n\t}" \
        :: "r"(mb), "r"(par) : "memory"); \
} while (0)
#define ST_ASYNC8(da, v, mb) \
    asm volatile("st.async.shared::cluster.mbarrier::complete_tx::bytes.b64 [%0], %1, [%2];" \
                 :: "r"(da), "l"(v), "r"(mb) : "memory")

// acc += W * src over KN k-rows (pointers pre-offset to slice start + lroff).
template <int KN>
__device__ __forceinline__ void accumH(ull acc[4][4], const float* __restrict__ Wp,
                                       const float* __restrict__ Sp) {
#pragma unroll
    for (int k = 0; k < KN; k++) {
        float4 wv = *(const float4*)(Wp + k * HH);
        ulonglong2 sa = *(const ulonglong2*)(Sp + k * BC);
        ulonglong2 sb = *(const ulonglong2*)(Sp + k * BC + 4);
        ull w0 = bcast2(wv.x), w1 = bcast2(wv.y), w2 = bcast2(wv.z), w3 = bcast2(wv.w);
        fma2(acc[0][0], w0, sa.x); fma2(acc[0][1], w0, sa.y);
        fma2(acc[0][2], w0, sb.x); fma2(acc[0][3], w0, sb.y);
        fma2(acc[1][0], w1, sa.x); fma2(acc[1][1], w1, sa.y);
        fma2(acc[1][2], w1, sb.x); fma2(acc[1][3], w1, sb.y);
        fma2(acc[2][0], w2, sa.x); fma2(acc[2][1], w2, sa.y);
        fma2(acc[2][2], w2, sb.x); fma2(acc[2][3], w2, sb.y);
        fma2(acc[3][0], w3, sa.x); fma2(acc[3][1], w3, sa.y);
        fma2(acc[3][2], w3, sb.x); fma2(acc[3][3], w3, sb.y);
    }
}

// Fused dual accumulate over KA k-rows: a1 += W1*src, a0 += W0*src.
template <int KA>
__device__ __forceinline__ void accumA(ull a1[4][4], ull a0[4][4],
                                       const float* __restrict__ Wp1,
                                       const float* __restrict__ Wp0,
                                       const float* __restrict__ Sp) {
#pragma unroll
    for (int k = 0; k < KA; k++) {
        float4 w1 = *(const float4*)(Wp1 + k * HH);
        float4 w0 = *(const float4*)(Wp0 + k * HH);
        ulonglong2 sa = *(const ulonglong2*)(Sp + k * BC);
        ulonglong2 sb = *(const ulonglong2*)(Sp + k * BC + 4);
        ull b0 = bcast2(w1.x), b1 = bcast2(w1.y), b2 = bcast2(w1.z), b3 = bcast2(w1.w);
        fma2(a1[0][0], b0, sa.x); fma2(a1[0][1], b0, sa.y);
        fma2(a1[0][2], b0, sb.x); fma2(a1[0][3], b0, sb.y);
        fma2(a1[1][0], b1, sa.x); fma2(a1[1][1], b1, sa.y);
        fma2(a1[1][2], b1, sb.x); fma2(a1[1][3], b1, sb.y);
        fma2(a1[2][0], b2, sa.x); fma2(a1[2][1], b2, sa.y);
        fma2(a1[2][2], b2, sb.x); fma2(a1[2][3], b2, sb.y);
        fma2(a1[3][0], b3, sa.x); fma2(a1[3][1], b3, sa.y);
        fma2(a1[3][2], b3, sb.x); fma2(a1[3][3], b3, sb.y);
        ull c0 = bcast2(w0.x), c1 = bcast2(w0.y), c2 = bcast2(w0.z), c3 = bcast2(w0.w);
        fma2(a0[0][0], c0, sa.x); fma2(a0[0][1], c0, sa.y);
        fma2(a0[0][2], c0, sb.x); fma2(a0[0][3], c0, sb.y);
        fma2(a0[1][0], c1, sa.x); fma2(a0[1][1], c1, sa.y);
        fma2(a0[1][2], c1, sb.x); fma2(a0[1][3], c1, sb.y);
        fma2(a0[2][0], c2, sa.x); fma2(a0[2][1], c2, sa.y);
        fma2(a0[2][2], c2, sb.x); fma2(a0[2][3], c2, sb.y);
        fma2(a0[3][0], c3, sa.x); fma2(a0[3][1], c3, sa.y);
        fma2(a0[3][2], c3, sb.x); fma2(a0[3][3], c3, sb.y);
    }
}

// Last 2 k-rows: a1 += W1*src, parking src in sreg[8]. Pointers pre-offset.
__device__ __forceinline__ void accumB2(ull a1[4][4], const float* __restrict__ Wp1,
                                        const float* __restrict__ Sp,
                                        ull* __restrict__ sreg) {
#pragma unroll
    for (int k = 0; k < 2; k++) {
        float4 w1 = *(const float4*)(Wp1 + k * HH);
        ulonglong2 sa = *(const ulonglong2*)(Sp + k * BC);
        ulonglong2 sb = *(const ulonglong2*)(Sp + k * BC + 4);
        sreg[k * 4 + 0] = sa.x; sreg[k * 4 + 1] = sa.y;
        sreg[k * 4 + 2] = sb.x; sreg[k * 4 + 3] = sb.y;
        ull b0 = bcast2(w1.x), b1 = bcast2(w1.y), b2 = bcast2(w1.z), b3 = bcast2(w1.w);
        fma2(a1[0][0], b0, sa.x); fma2(a1[0][1], b0, sa.y);
        fma2(a1[0][2], b0, sb.x); fma2(a1[0][3], b0, sb.y);
        fma2(a1[1][0], b1, sa.x); fma2(a1[1][1], b1, sa.y);
        fma2(a1[1][2], b1, sb.x); fma2(a1[1][3], b1, sb.y);
        fma2(a1[2][0], b2, sa.x); fma2(a1[2][1], b2, sa.y);
        fma2(a1[2][2], b2, sb.x); fma2(a1[2][3], b2, sb.y);
        fma2(a1[3][0], b3, sa.x); fma2(a1[3][1], b3, sa.y);
        fma2(a1[3][2], b3, sb.x); fma2(a1[3][3], b3, sb.y);
    }
}

// Last 2 k-rows: a0 += W0*sreg (weight loads only). Pointer pre-offset.
__device__ __forceinline__ void accumC2(ull a0[4][4], const float* __restrict__ Wp0,
                                        const ull* __restrict__ sreg) {
#pragma unroll
    for (int k = 0; k < 2; k++) {
        float4 w0 = *(const float4*)(Wp0 + k * HH);
        ull s0 = sreg[k * 4 + 0], s1 = sreg[k * 4 + 1];
        ull s2 = sreg[k * 4 + 2], s3 = sreg[k * 4 + 3];
        ull c0 = bcast2(w0.x), c1 = bcast2(w0.y), c2 = bcast2(w0.z), c3 = bcast2(w0.w);
        fma2(a0[0][0], c0, s0); fma2(a0[0][1], c0, s1);
        fma2(a0[0][2], c0, s2); fma2(a0[0][3], c0, s3);
        fma2(a0[1][0], c1, s0); fma2(a0[1][1], c1, s1);
        fma2(a0[1][2], c1, s2); fma2(a0[1][3], c1, s3);
        fma2(a0[2][0], c2, s0); fma2(a0[2][1], c2, s1);
        fma2(a0[2][2], c2, s2); fma2(a0[2][3], c2, s3);
        fma2(a0[3][0], c3, s0); fma2(a0[3][1], c3, s1);
        fma2(a0[3][2], c3, s2); fma2(a0[3][3], c3, s3);
    }
}

// Reduce + gates + c update + st.async h to all ranks (tx-counted).
template <bool HEAD, int BARID>
__device__ __forceinline__ void rus(ull acc[4][4], Smem* sm, const float* __restrict__ bias,
                                    float2& cp, const uint32_t* dbase,
                                    uint32_t h_off, uint32_t mb_off,
                                    uint32_t hd_off, uint32_t mbh_off,
                                    int q, int warp, int lane, float wl) {
    ull o4[4];
    {
        const bool h8 = lane & 8;
        ull m0[4], m1[4];
#pragma unroll
        for (int g = 0; g < 4; g++) {
            ull s0 = h8 ? acc[g][0] : acc[g][2];
            ull s1 = h8 ? acc[g][1] : acc[g][3];
            ull r0 = __shfl_xor_sync(0xffffffffu, s0, 8);
            ull r1 = __shfl_xor_sync(0xffffffffu, s1, 8);
            m0[g] = add2(h8 ? acc[g][2] : acc[g][0], r0);
            m1[g] = add2(h8 ? acc[g][3] : acc[g][1], r1);
        }
        const bool h16 = lane & 16;
#pragma unroll
        for (int g = 0; g < 4; g++) {
            ull s = h16 ? m0[g] : m1[g];
            ull r = __shfl_xor_sync(0xffffffffu, s, 16);
            o4[g] = add2(h16 ? m1[g] : m0[g], r);
        }
    }
    const int jjl = lane & 7, wg = warp & 3, ksr = warp >> 2;
    const int jj = wg * 8 + jjl;
    const int pi = ((lane >> 3) & 1) * 2 + ((lane >> 4) & 1);
    if (ksr > 0) {
        ull* slot = sm->red + ((ksr - 1) * 32 + jj) * 16 + (pi ^ (jjl & 3)) * 4;
        *(ulonglong2*)(slot)     = make_ulonglong2(o4[0], o4[1]);
        *(ulonglong2*)(slot + 2) = make_ulonglong2(o4[2], o4[3]);
        asm volatile("bar.arrive %0, %1;" :: "n"(BARID), "n"(NT) : "memory");
    } else {
        asm volatile("bar.sync %0, %1;" :: "n"(BARID), "n"(NT) : "memory");
        ull* slot = sm->red + jj * 16 + (pi ^ (jjl & 3)) * 4;
#pragma unroll
        for (int r = 0; r < 3; r++) {
            ulonglong2 v0 = *(ulonglong2*)(slot + r * 512);
            ulonglong2 v1 = *(ulonglong2*)(slot + r * 512 + 2);
            o4[0] = add2(o4[0], v0.x); o4[1] = add2(o4[1], v0.y);
            o4[2] = add2(o4[2], v1.x); o4[3] = add2(o4[3], v1.y);
        }
        float4 bq = *(const float4*)(bias + jj * 4);
        float xi0, xi1, xf0, xf1, xg0, xg1, xo0, xo1;
        unpack2(o4[0], xi0, xi1); unpack2(o4[1], xf0, xf1);
        unpack2(o4[2], xg0, xg1); unpack2(o4[3], xo0, xo1);
        float i0 = sig_f(xi0 + bq.x), i1 = sig_f(xi1 + bq.x);
        float f0 = sig_f(xf0 + bq.y), f1 = sig_f(xf1 + bq.y);
        float g0 = tanh_f(xg0 + bq.z), g1 = tanh_f(xg1 + bq.z);
        float o0 = sig_f(xo0 + bq.w), o1 = sig_f(xo1 + bq.w);
        cp.x = f0 * cp.x + i0 * g0;
        cp.y = f1 * cp.y + i1 * g1;
        float h0v = o0 * tanh_f(cp.x), h1v = o1 * tanh_f(cp.y);
        ull hp = pack2(h0v, h1v);
        uint32_t row = h_off + ((q * 32 + jj) * BC + pi * 2) * 4;
#pragma unroll
        for (int r2 = 0; r2 < CSIZE; r2++)
            ST_ASYNC8(dbase[r2] + row, hp, dbase[r2] + mb_off);
        if (HEAD) {
            ull hh = pack2(fmaxf(h0v, 0.f) * wl, fmaxf(h1v, 0.f) * wl);
            hh = add2(hh, __shfl_xor_sync(0xffffffffu, hh, 1));
            hh = add2(hh, __shfl_xor_sync(0xffffffffu, hh, 2));
            hh = add2(hh, __shfl_xor_sync(0xffffffffu, hh, 4));
            if (jjl == 0)
                ST_ASYNC8(dbase[0] + hd_off + ((q * 4 + wg) * 4 + pi) * 8, hh,
                          dbase[0] + mbh_off);
        }
    }
}

__device__ __forceinline__ void head_out(Smem* sm, int par, float* __restrict__ out,
                                         int bbase, float blinr, int lane, int tt) {
    int g = lane >> 4, l = lane & 15;
    float2 v0 = sm->headred[par][l][g * 2 + 0];
    float2 v1 = sm->headred[par][l][g * 2 + 1];
    ull a = pack2(v0.x, v0.y), b = pack2(v1.x, v1.y);
#pragma unroll
    for (int m = 1; m <= 8; m <<= 1) {
        a = add2(a, __shfl_xor_sync(0xffffffffu, a, m));
        b = add2(b, __shfl_xor_sync(0xffffffffu, b, m));
    }
    if (l == 0) {
        float a0, a1, b0, b1;
        unpack2(a, a0, a1); unpack2(b, b0, b1);
        size_t base = (size_t)(bbase + g * 4) * TT + tt;
        out[base]          = a0 + blinr;
        out[base + TT]     = a1 + blinr;
        out[base + 2 * TT] = b0 + blinr;
        out[base + 3 * TT] = b1 + blinr;
    }
}

__global__ void __cluster_dims__(CSIZE, 1, 1) __launch_bounds__(NT, 1)
lstm_kernel(const float* __restrict__ x,
            const float* __restrict__ Wih0, const float* __restrict__ Whh0,
            const float* __restrict__ bih0, const float* __restrict__ bhh0,
            const float* __restrict__ Wih1, const float* __restrict__ Whh1,
            const float* __restrict__ bih1, const float* __restrict__ bhh1,
            const float* __restrict__ Wlin, const float* __restrict__ blin,
            float* __restrict__ out) {
    extern __shared__ char smem_bytes[];
    Smem* sm = (Smem*)smem_bytes;
    cg::cluster_group cl = cg::this_cluster();
    const int q = cl.block_rank();
    const int tid = threadIdx.x, warp = tid >> 5, lane = tid & 31;
    const int bbase = (blockIdx.x / CSIZE) * BC;

    for (int idx = tid; idx < HH * HH; idx += NT) {
        int k = idx >> 7, lr = idx & 127;
        int g = lr & 3, j2 = lr >> 2;
        int grow = g * HH + q * 32 + j2;
        sm->Whh0[k * HH + lr] = Whh0[grow * HH + k];
        sm->Wih1[k * HH + lr] = Wih1[grow * HH + k];
        sm->Whh1[k * HH + lr] = Whh1[grow * HH + k];
    }
    for (int lr = tid; lr < HH; lr += NT) {
        int g = lr & 3, j2 = lr >> 2;
        int grow = g * HH + q * 32 + j2;
        sm->b0[lr] = bih0[grow] + bhh0[grow];
        sm->b1[lr] = bih1[grow] + bhh1[grow];
    }
    for (int i = tid; i < 2 * HH * BC; i += NT) {
        ((float*)sm->h0buf)[i] = 0.0f;
        ((float*)sm->h1buf)[i] = 0.0f;
    }
    const int jj = (warp & 3) * 8 + (lane & 7);
    const int lroff = jj * 4;
    const int ks = (warp >> 2) * 4 + ((lane >> 3) & 3);     // 0..15
    // Uneven k-split: gate warps (ks<4) take 5-k slices, producers 9-k.
    const bool gatew = (warp < 4);
    const int kstart = gatew ? ks * 5 : 20 + (ks - 4) * 9;
    const int woff = kstart * HH + lroff;
    const int soff = kstart * BC;

    ull wih0p[4];
#pragma unroll
    for (int g = 0; g < 4; g++)
        wih0p[g] = bcast2(Wih0[(g * HH + q * 32 + jj) * II + ks]);
    const float wl = Wlin[q * 32 + jj];
    const float blinr = blin[0];

    const uint32_t sb = smem_u32(smem_bytes);
    uint32_t dbase[CSIZE];
#pragma unroll
    for (int r = 0; r < CSIZE; r++) dbase[r] = mapa_rank(sb, r);
    const uint32_t h0off = (uint32_t)((char*)&sm->h0buf[0][0] - smem_bytes);
    const uint32_t h1off = (uint32_t)((char*)&sm->h1buf[0][0] - smem_bytes);
    const uint32_t hroff = (uint32_t)((char*)&sm->headred[0][0][0] - smem_bytes);
    const uint32_t mboff = (uint32_t)((char*)&sm->mbars[0] - smem_bytes);
    const uint32_t mb_l = sb + mboff;

    if (tid == 0) {
#pragma unroll
        for (int i = 0; i < 6; i++) MB_INIT(mb_l + i * 8);
        MB_ARM(mb_l + 0, 4096); MB_ARM(mb_l + 8, 4096);
        MB_ARM(mb_l + 16, 4096); MB_ARM(mb_l + 24, 4096);
        if (q == 0) { MB_ARM(mb_l + 32, 512); MB_ARM(mb_l + 40, 512); }
    }
    __syncthreads();
    cl.sync();

    float2 c0 = {0.f, 0.f}, c1 = {0.f, 0.f};
    const float* xbase = x + (size_t)bbase * TT * II + ks;

    float xr[8];
#pragma unroll
    for (int b = 0; b < 8; b++) xr[b] = __ldg(xbase + b * TT * II);
    ull acc0[4][4];
    {
        ull s0 = pack2(xr[0], xr[1]), s1 = pack2(xr[2], xr[3]);
        ull s2 = pack2(xr[4], xr[5]), s3 = pack2(xr[6], xr[7]);
#pragma unroll
        for (int g = 0; g < 4; g++) {
            acc0[g][0] = 0ull; acc0[g][1] = 0ull; acc0[g][2] = 0ull; acc0[g][3] = 0ull;
            fma2(acc0[g][0], wih0p[g], s0); fma2(acc0[g][1], wih0p[g], s1);
            fma2(acc0[g][2], wih0p[g], s2); fma2(acc0[g][3], wih0p[g], s3);
        }
    }

    for (int t = 0; t < TT; t++) {
        const int par = t & 1, nxt = par ^ 1;
        const uint32_t pw0 = (t >> 1) & 1;
        const uint32_t pw1 = ((t - 1) >> 1) & 1;

        // prefetch x(t+1)
        {
            const float* xp = xbase + (size_t)((t + 1 < TT) ? t + 1 : TT - 1) * II;
#pragma unroll
            for (int b = 0; b < 8; b++) xr[b] = __ldg(xp + b * TT * II);
        }

        if (t > 0) {
            MB_WAIT(mb_l + 16 + nxt * 8, pw1);
            if (tid == 0) MB_ARM(mb_l + 16 + nxt * 8, 4096);
        }

        // layer-0 reduce -> push h0(t)
        rus<false, 1>(acc0, sm, sm->b0, c0, dbase,
                      h0off + par * (HH * BC * 4), mboff + par * 8,
                      0, 0, q, warp, lane, 0.f);

        ull acc1[4][4];
#pragma unroll
        for (int g = 0; g < 4; g++) {
            acc1[g][0] = 0ull; acc1[g][1] = 0ull; acc1[g][2] = 0ull; acc1[g][3] = 0ull;
        }
        if (gatew) accumH<5>(acc1, sm->Whh1 + woff, sm->h1buf[nxt] + soff);
        else       accumH<9>(acc1, sm->Whh1 + woff, sm->h1buf[nxt] + soff);

        // acc0 = Wih0 * x(t+1)
        {
            ull s0 = pack2(xr[0], xr[1]), s1 = pack2(xr[2], xr[3]);
            ull s2 = pack2(xr[4], xr[5]), s3 = pack2(xr[6], xr[7]);
#pragma unroll
            for (int g = 0; g < 4; g++) {
                acc0[g][0] = 0ull; acc0[g][1] = 0ull; acc0[g][2] = 0ull; acc0[g][3] = 0ull;
                fma2(acc0[g][0], wih0p[g], s0); fma2(acc0[g][1], wih0p[g], s1);
                fma2(acc0[g][2], wih0p[g], s2); fma2(acc0[g][3], wih0p[g], s3);
            }
        }

        MB_WAIT(mb_l + par * 8, pw0);
        if (tid == 0) MB_ARM(mb_l + par * 8, 4096);

        // h0(t) read once: dual-fused (all but last 2 k), parked last 2
        ull sreg[8];
        const float* h0p = sm->h0buf[par] + soff;
        if (gatew) {
            accumA<3>(acc1, acc0, sm->Wih1 + woff, sm->Whh0 + woff, h0p);
            accumB2(acc1, sm->Wih1 + woff + 3 * HH, h0p + 3 * BC, sreg);
        } else {
            accumA<7>(acc1, acc0, sm->Wih1 + woff, sm->Whh0 + woff, h0p);
            accumB2(acc1, sm->Wih1 + woff + 7 * HH, h0p + 7 * BC, sreg);
        }

        rus<true, 2>(acc1, sm, sm->b1, c1, dbase,
                     h1off + par * (HH * BC * 4), mboff + 16 + par * 8,
                     hroff + par * 512, mboff + 32 + par * 8,
                     q, warp, lane, wl);

        if (gatew) accumC2(acc0, sm->Whh0 + woff + 3 * HH, sreg);
        else       accumC2(acc0, sm->Whh0 + woff + 7 * HH, sreg);

        if (q == 0 && warp == 15 && t > 0) {
            MB_WAIT(mb_l + 32 + nxt * 8, pw1);
            if (lane == 0) MB_ARM(mb_l + 32 + nxt * 8, 512);
            head_out(sm, nxt, out, bbase, blinr, lane, t - 1);
        }
    }
    if (q == 0 && warp == 15) {
        MB_WAIT(mb_l + 32 + ((TT - 1) & 1) * 8, ((TT - 1) >> 1) & 1);
        head_out(sm, (TT - 1) & 1, out, bbase, blinr, lane, TT - 1);
    }
    cl.sync();
}

extern "C" void kernel_launch(void* const* d_in, const int* in_sizes, int n_in,
                              void* d_out, int out_size) {
    const float* x    = (const float*)d_in[0];
    const float* Wih0 = (const float*)d_in[1];
    const float* Whh0 = (const float*)d_in[2];
    const float* bih0 = (const float*)d_in[3];
    const float* bhh0 = (const float*)d_in[4];
    const float* Wih1 = (const float*)d_in[5];
    const float* Whh1 = (const float*)d_in[6];
    const float* bih1 = (const float*)d_in[7];
    const float* bhh1 = (const float*)d_in[8];
    const float* Wlin = (const float*)d_in[9];
    const float* blin = (const float*)d_in[10];
    float* out = (float*)d_out;

    size_t smem = sizeof(Smem);
    cudaFuncSetAttribute(lstm_kernel, cudaFuncAttributeMaxDynamicSharedMemorySize,
                         (int)smem);
    lstm_kernel<<<NCTAS, NT, smem>>>(x, Wih0, Whh0, bih0, bhh0,
                                     Wih1, Whh1, bih1, bhh1,
                                     Wlin, blin, out);
}